// round 5
// baseline (speedup 1.0000x reference)
#include <cuda_runtime.h>
#include <cstdint>

#define T_LEN  4096
#define NTH    256
#define PER    8                  // steps per thread (half sequence / 256 threads)
#define HALF   2048               // steps per CTA (cluster of 2 per sequence)
#define PITCH  257                // smem row pitch for output staging

#define DTF    (1.0f / 200.0f)
#define DT2H   (DTF * DTF * 0.5f)
#define STEPDT ((float)PER * DTF)

struct Carry {
    float R0,R1,R2,R3,R4,R5,R6,R7,R8;
    float vx,vy,vz, px,py,pz;
};

__device__ __forceinline__ void set_identity(Carry& C) {
    C.R0=1.f; C.R1=0.f; C.R2=0.f; C.R3=0.f; C.R4=1.f; C.R5=0.f;
    C.R6=0.f; C.R7=0.f; C.R8=1.f;
    C.vx=C.vy=C.vz=0.f; C.px=C.py=C.pz=0.f;
}

// one recurrence step: R *= Rk(w);  Ra = R a;  v += Ra dt;  p += v dt + Ra dt^2/2
__device__ __forceinline__ void step_update(Carry& C,
                                            float wx, float wy, float wz,
                                            float ax, float ay, float az) {
    // Rodrigues via Taylor (theta <= ~0.03): R = I + A*K(w) + B*(w w^T - |w|^2 I)
    float n2  = fmaf(wx, wx, fmaf(wy, wy, wz * wz));
    float th2 = n2 * (DTF * DTF);
    float A   = DTF * (1.0f + th2 * (-1.0f / 6.0f + th2 * (1.0f / 120.0f)));
    float Bc  = (DTF * DTF) * (0.5f + th2 * (-1.0f / 24.0f + th2 * (1.0f / 720.0f)));
    float xy = wx * wy, xz = wx * wz, yz = wy * wz;
    float k0 = 1.0f + Bc * (wx * wx - n2);
    float k1 = Bc * xy - A * wz;
    float k2 = Bc * xz + A * wy;
    float k3 = Bc * xy + A * wz;
    float k4 = 1.0f + Bc * (wy * wy - n2);
    float k5 = Bc * yz - A * wx;
    float k6 = Bc * xz - A * wy;
    float k7 = Bc * yz + A * wx;
    float k8 = 1.0f + Bc * (wz * wz - n2);

    float n0 = C.R0*k0 + C.R1*k3 + C.R2*k6;
    float n1 = C.R0*k1 + C.R1*k4 + C.R2*k7;
    float n2_= C.R0*k2 + C.R1*k5 + C.R2*k8;
    float n3 = C.R3*k0 + C.R4*k3 + C.R5*k6;
    float n4 = C.R3*k1 + C.R4*k4 + C.R5*k7;
    float n5 = C.R3*k2 + C.R4*k5 + C.R5*k8;
    float n6 = C.R6*k0 + C.R7*k3 + C.R8*k6;
    float n7 = C.R6*k1 + C.R7*k4 + C.R8*k7;
    float n8 = C.R6*k2 + C.R7*k5 + C.R8*k8;
    C.R0=n0; C.R1=n1; C.R2=n2_; C.R3=n3; C.R4=n4; C.R5=n5; C.R6=n6; C.R7=n7; C.R8=n8;

    float Rax = C.R0*ax + C.R1*ay + C.R2*az;
    float Ray = C.R3*ax + C.R4*ay + C.R5*az;
    float Raz = C.R6*ax + C.R7*ay + C.R8*az;

    C.vx += Rax * DTF; C.vy += Ray * DTF; C.vz += Raz * DTF;
    C.px += C.vx * DTF + Rax * DT2H;
    C.py += C.vy * DTF + Ray * DT2H;
    C.pz += C.vz * DTF + Raz * DT2H;
}

// C_right = L  compose  C_right   (L earlier in time), ndt_right = time span of C_right
__device__ __forceinline__ void compose_left(Carry& C, const float* L, float ndt_right) {
    float t0 = L[0]*C.R0 + L[1]*C.R3 + L[2]*C.R6;
    float t1 = L[0]*C.R1 + L[1]*C.R4 + L[2]*C.R7;
    float t2 = L[0]*C.R2 + L[1]*C.R5 + L[2]*C.R8;
    float t3 = L[3]*C.R0 + L[4]*C.R3 + L[5]*C.R6;
    float t4 = L[3]*C.R1 + L[4]*C.R4 + L[5]*C.R7;
    float t5 = L[3]*C.R2 + L[4]*C.R5 + L[5]*C.R8;
    float t6 = L[6]*C.R0 + L[7]*C.R3 + L[8]*C.R6;
    float t7 = L[6]*C.R1 + L[7]*C.R4 + L[8]*C.R7;
    float t8 = L[6]*C.R2 + L[7]*C.R5 + L[8]*C.R8;

    float nvx = L[9]  + L[0]*C.vx + L[1]*C.vy + L[2]*C.vz;
    float nvy = L[10] + L[3]*C.vx + L[4]*C.vy + L[5]*C.vz;
    float nvz = L[11] + L[6]*C.vx + L[7]*C.vy + L[8]*C.vz;

    float npx = L[12] + L[9]*ndt_right  + L[0]*C.px + L[1]*C.py + L[2]*C.pz;
    float npy = L[13] + L[10]*ndt_right + L[3]*C.px + L[4]*C.py + L[5]*C.pz;
    float npz = L[14] + L[11]*ndt_right + L[6]*C.px + L[7]*C.py + L[8]*C.pz;

    C.R0=t0; C.R1=t1; C.R2=t2; C.R3=t3; C.R4=t4; C.R5=t5; C.R6=t6; C.R7=t7; C.R8=t8;
    C.vx=nvx; C.vy=nvy; C.vz=nvz;
    C.px=npx; C.py=npy; C.pz=npz;
}

__device__ __forceinline__ void store_elem(float* me, const Carry& C) {
    me[0]=C.R0; me[1]=C.R1; me[2]=C.R2; me[3]=C.R3; me[4]=C.R4; me[5]=C.R5;
    me[6]=C.R6; me[7]=C.R7; me[8]=C.R8;
    me[9]=C.vx; me[10]=C.vy; me[11]=C.vz;
    me[12]=C.px; me[13]=C.py; me[14]=C.pz;
}

__device__ __forceinline__ uint32_t smem_u32(const void* p) {
    uint32_t a;
    asm("{ .reg .u64 t; cvta.to.shared.u64 t, %1; cvt.u32.u64 %0, t; }" : "=r"(a) : "l"(p));
    return a;
}

__global__ void __launch_bounds__(NTH, 3) __cluster_dims__(2, 1, 1)
preint_kernel(const float* __restrict__ in, float* __restrict__ out) {
    // output staging (2 steps x 16 channels, transposed); also the scan buffer
    __shared__ float s_out[32 * PITCH];     // 32896 B
    __shared__ float s_xchg[16];            // cross-CTA aggregate

    const int tid = threadIdx.x;
    uint32_t rank;
    asm("mov.u32 %0, %%cluster_ctarank;" : "=r"(rank));
    const int b = blockIdx.x >> 1;

    const size_t base_step = (size_t)b * T_LEN + (size_t)rank * HALF + (size_t)tid * PER;
    const float4* ip = (const float4*)in + ((base_step * 6) >> 2);  // 12 float4 per thread

    Carry C;
    set_identity(C);

    // ---------------- Phase 1: thread-local aggregate, direct float4 loads ----------------
#pragma unroll
    for (int g = 0; g < 2; g++) {
        float4 d0 = ip[g*6+0], d1 = ip[g*6+1], d2 = ip[g*6+2];
        float4 d3 = ip[g*6+3], d4 = ip[g*6+4], d5 = ip[g*6+5];
        step_update(C, d0.x, d0.y, d0.z, d0.w, d1.x, d1.y);
        step_update(C, d1.z, d1.w, d2.x, d2.y, d2.z, d2.w);
        step_update(C, d3.x, d3.y, d3.z, d3.w, d4.x, d4.y);
        step_update(C, d4.z, d4.w, d5.x, d5.y, d5.z, d5.w);
    }

    // ---------------- Block-level inclusive scan (Hillis-Steele, 8 rounds) ----------------
    // element = 15 floats at pitch 17 (conflict-free); ndt is implicit: min(d, tid+1)*STEPDT
    store_elem(s_out + tid * 17, C);
    __syncthreads();

    for (int d = 1; d < NTH; d <<= 1) {
        float L[15];
        const bool act = (tid >= d);
        if (act) {
            const float* l = s_out + (tid - d) * 17;
#pragma unroll
            for (int i = 0; i < 15; i++) L[i] = l[i];
        }
        __syncthreads();
        if (act) {
            int cnt = d < (tid + 1) ? d : (tid + 1);
            compose_left(C, L, (float)cnt * STEPDT);
            store_elem(s_out + tid * 17, C);
        }
        __syncthreads();
    }

    // rank 0 publishes its block total (inclusive of tid 255) for rank 1
    if (rank == 0 && tid == NTH - 1) store_elem(s_xchg, C);

    // exclusive prefix = inclusive of tid-1
    if (tid == 0) set_identity(C);
    else {
        const float* l = s_out + (tid - 1) * 17;
        C.R0=l[0]; C.R1=l[1]; C.R2=l[2]; C.R3=l[3]; C.R4=l[4]; C.R5=l[5];
        C.R6=l[6]; C.R7=l[7]; C.R8=l[8];
        C.vx=l[9]; C.vy=l[10]; C.vz=l[11];
        C.px=l[12]; C.py=l[13]; C.pz=l[14];
    }

    // ---------------- Cross-CTA prefix exchange (cluster of 2) ----------------
    asm volatile("barrier.cluster.arrive.aligned;" ::: "memory");
    asm volatile("barrier.cluster.wait.aligned;"   ::: "memory");

    if (rank == 1 && tid < 15) {
        // pull rank 0's aggregate into our local s_xchg
        uint32_t lcl = smem_u32(&s_xchg[tid]);
        uint32_t rem;
        asm("mapa.shared::cluster.u32 %0, %1, %2;" : "=r"(rem) : "r"(lcl), "r"(0));
        float v;
        asm volatile("ld.shared::cluster.f32 %0, [%1];" : "=f"(v) : "r"(rem));
        s_xchg[tid] = v;
    }
    __syncthreads();
    if (rank == 1) {
        float L[15];
#pragma unroll
        for (int i = 0; i < 15; i++) L[i] = s_xchg[i];
        compose_left(C, L, (float)(tid * PER) * DTF);
    }
    // second cluster barrier: rank 0 must not exit before rank 1 read its smem;
    // also orders the exclusive-prefix smem reads before phase-2 reuse of s_out
    asm volatile("barrier.cluster.arrive.aligned;" ::: "memory");
    asm volatile("barrier.cluster.wait.aligned;"   ::: "memory");

    // ---------------- Phase 2: replay with prefix, staged + coalesced output ----------------
    float4* out4 = (float4*)out + ((size_t)b * T_LEN + (size_t)rank * HALF) * 4;

#pragma unroll
    for (int g = 0; g < 2; g++) {
        float4 d0 = ip[g*6+0], d1 = ip[g*6+1], d2 = ip[g*6+2];
        float4 d3 = ip[g*6+3], d4 = ip[g*6+4], d5 = ip[g*6+5];
        float wxs[4] = {d0.x, d1.z, d3.x, d4.z};
        float wys[4] = {d0.y, d1.w, d3.y, d4.w};
        float wzs[4] = {d0.z, d2.x, d3.z, d5.x};
        float axs[4] = {d0.w, d2.y, d3.w, d5.y};
        float ays[4] = {d1.x, d2.z, d4.x, d5.z};
        float azs[4] = {d1.y, d2.w, d4.y, d5.w};

#pragma unroll
        for (int k = 0; k < 4; k++) {
            step_update(C, wxs[k], wys[k], wzs[k], axs[k], ays[k], azs[k]);

            // quaternion from R (half-angle identities; matches reference clip+EPS path)
            float tr = C.R0 + C.R4 + C.R8;
            float cc = 0.5f * (tr - 1.0f);
            cc = fminf(fmaxf(cc, -1.0f + 1e-7f), 1.0f - 1e-7f);
            float t   = 0.5f * (1.0f + cc);
            float rin = rsqrtf(t);
            float qw  = t * rin;
            float fq  = 0.25f * rin;
            float qx  = (C.R7 - C.R5) * fq;
            float qy  = (C.R2 - C.R6) * fq;
            float qz  = (C.R3 - C.R1) * fq;

            float* dst = s_out + ((k & 1) * 16) * PITCH + tid;
            dst[0*PITCH]  = wxs[k]; dst[1*PITCH]  = wys[k]; dst[2*PITCH]  = wzs[k];
            dst[3*PITCH]  = axs[k]; dst[4*PITCH]  = ays[k]; dst[5*PITCH]  = azs[k];
            dst[6*PITCH]  = C.px;   dst[7*PITCH]  = C.py;   dst[8*PITCH]  = C.pz;
            dst[9*PITCH]  = qw;     dst[10*PITCH] = qx;     dst[11*PITCH] = qy;
            dst[12*PITCH] = qz;
            dst[13*PITCH] = C.vx;   dst[14*PITCH] = C.vy;   dst[15*PITCH] = C.vz;

            if (k & 1) {
                __syncthreads();
                // coalesced flush of 2 steps x 256 owners = 2048 float4
                int t2 = g * 2 + (k >> 1);
#pragma unroll
                for (int r = 0; r < 8; r++) {
                    int f  = tid + NTH * r;
                    int o  = f >> 3;
                    int mq = f & 7;
                    const float* s = s_out + (mq * 4) * PITCH + o;
                    float4 v = make_float4(s[0*PITCH], s[1*PITCH], s[2*PITCH], s[3*PITCH]);
                    out4[(size_t)o * (PER * 4) + t2 * 8 + mq] = v;
                }
                __syncthreads();
            }
        }
    }
}

extern "C" void kernel_launch(void* const* d_in, const int* in_sizes, int n_in,
                              void* d_out, int out_size) {
    const float* in = (const float*)d_in[0];
    float* out = (float*)d_out;
    int Bn = in_sizes[0] / (T_LEN * 6);   // 512 for the reference shapes
    preint_kernel<<<Bn * 2, NTH>>>(in, out);
}

// round 6
// speedup vs baseline: 1.2965x; 1.2965x over previous
#include <cuda_runtime.h>
#include <cstdint>

#define T_LEN  4096
#define NTH    512
#define PER    8                  // steps per thread; input held in registers
#define PITCH  513                // smem row pitch for output staging (513 % 32 == 1)

#define DTF    (1.0f / 200.0f)
#define DT2H   (DTF * DTF * 0.5f)
#define STEPDT ((float)PER * DTF)

struct Carry {
    float R0,R1,R2,R3,R4,R5,R6,R7,R8;
    float vx,vy,vz, px,py,pz;
};

__device__ __forceinline__ void set_identity(Carry& C) {
    C.R0=1.f; C.R1=0.f; C.R2=0.f; C.R3=0.f; C.R4=1.f; C.R5=0.f;
    C.R6=0.f; C.R7=0.f; C.R8=1.f;
    C.vx=C.vy=C.vz=0.f; C.px=C.py=C.pz=0.f;
}

// one recurrence step: R *= Rk(w);  Ra = R a;  v += Ra dt;  p += v dt + Ra dt^2/2
__device__ __forceinline__ void step_update(Carry& C,
                                            float wx, float wy, float wz,
                                            float ax, float ay, float az) {
    // Rodrigues via Taylor (theta <= ~0.03): R = I + A*K(w) + B*(w w^T - |w|^2 I)
    float n2  = fmaf(wx, wx, fmaf(wy, wy, wz * wz));
    float th2 = n2 * (DTF * DTF);
    float A   = DTF * (1.0f + th2 * (-1.0f / 6.0f + th2 * (1.0f / 120.0f)));
    float Bc  = (DTF * DTF) * (0.5f + th2 * (-1.0f / 24.0f + th2 * (1.0f / 720.0f)));
    float xy = wx * wy, xz = wx * wz, yz = wy * wz;
    float k0 = 1.0f + Bc * (wx * wx - n2);
    float k1 = Bc * xy - A * wz;
    float k2 = Bc * xz + A * wy;
    float k3 = Bc * xy + A * wz;
    float k4 = 1.0f + Bc * (wy * wy - n2);
    float k5 = Bc * yz - A * wx;
    float k6 = Bc * xz - A * wy;
    float k7 = Bc * yz + A * wx;
    float k8 = 1.0f + Bc * (wz * wz - n2);

    float n0 = C.R0*k0 + C.R1*k3 + C.R2*k6;
    float n1 = C.R0*k1 + C.R1*k4 + C.R2*k7;
    float n2_= C.R0*k2 + C.R1*k5 + C.R2*k8;
    float n3 = C.R3*k0 + C.R4*k3 + C.R5*k6;
    float n4 = C.R3*k1 + C.R4*k4 + C.R5*k7;
    float n5 = C.R3*k2 + C.R4*k5 + C.R5*k8;
    float n6 = C.R6*k0 + C.R7*k3 + C.R8*k6;
    float n7 = C.R6*k1 + C.R7*k4 + C.R8*k7;
    float n8 = C.R6*k2 + C.R7*k5 + C.R8*k8;
    C.R0=n0; C.R1=n1; C.R2=n2_; C.R3=n3; C.R4=n4; C.R5=n5; C.R6=n6; C.R7=n7; C.R8=n8;

    float Rax = C.R0*ax + C.R1*ay + C.R2*az;
    float Ray = C.R3*ax + C.R4*ay + C.R5*az;
    float Raz = C.R6*ax + C.R7*ay + C.R8*az;

    C.vx += Rax * DTF; C.vy += Ray * DTF; C.vz += Raz * DTF;
    C.px += C.vx * DTF + Rax * DT2H;
    C.py += C.vy * DTF + Ray * DT2H;
    C.pz += C.vz * DTF + Raz * DT2H;
}

// C = L compose C  (L earlier in time); ndt_right = time span covered by C
__device__ __forceinline__ void compose_left(Carry& C, const float* L, float ndt_right) {
    float t0 = L[0]*C.R0 + L[1]*C.R3 + L[2]*C.R6;
    float t1 = L[0]*C.R1 + L[1]*C.R4 + L[2]*C.R7;
    float t2 = L[0]*C.R2 + L[1]*C.R5 + L[2]*C.R8;
    float t3 = L[3]*C.R0 + L[4]*C.R3 + L[5]*C.R6;
    float t4 = L[3]*C.R1 + L[4]*C.R4 + L[5]*C.R7;
    float t5 = L[3]*C.R2 + L[4]*C.R5 + L[5]*C.R8;
    float t6 = L[6]*C.R0 + L[7]*C.R3 + L[8]*C.R6;
    float t7 = L[6]*C.R1 + L[7]*C.R4 + L[8]*C.R7;
    float t8 = L[6]*C.R2 + L[7]*C.R5 + L[8]*C.R8;

    float nvx = L[9]  + L[0]*C.vx + L[1]*C.vy + L[2]*C.vz;
    float nvy = L[10] + L[3]*C.vx + L[4]*C.vy + L[5]*C.vz;
    float nvz = L[11] + L[6]*C.vx + L[7]*C.vy + L[8]*C.vz;

    float npx = L[12] + L[9]*ndt_right  + L[0]*C.px + L[1]*C.py + L[2]*C.pz;
    float npy = L[13] + L[10]*ndt_right + L[3]*C.px + L[4]*C.py + L[5]*C.pz;
    float npz = L[14] + L[11]*ndt_right + L[6]*C.px + L[7]*C.py + L[8]*C.pz;

    C.R0=t0; C.R1=t1; C.R2=t2; C.R3=t3; C.R4=t4; C.R5=t5; C.R6=t6; C.R7=t7; C.R8=t8;
    C.vx=nvx; C.vy=nvy; C.vz=nvz;
    C.px=npx; C.py=npy; C.pz=npz;
}

__device__ __forceinline__ void store_elem(float* me, const Carry& C) {
    me[0]=C.R0; me[1]=C.R1; me[2]=C.R2; me[3]=C.R3; me[4]=C.R4; me[5]=C.R5;
    me[6]=C.R6; me[7]=C.R7; me[8]=C.R8;
    me[9]=C.vx; me[10]=C.vy; me[11]=C.vz;
    me[12]=C.px; me[13]=C.py; me[14]=C.pz;
}

__global__ void __launch_bounds__(NTH, 1)
preint_kernel(const float* __restrict__ in, float* __restrict__ out) {
    // single smem buffer: scan storage (512 x 17 = 8704 floats) aliased with
    // output staging (32 rows x PITCH = 16416 floats). Sized for the larger.
    __shared__ float s_buf[32 * PITCH];

    const int b   = blockIdx.x;
    const int tid = threadIdx.x;

    // ---------------- Load input ONCE into registers (12 float4 per thread) ----------------
    const float4* ip = (const float4*)in + (size_t)b * (T_LEN * 6 / 4) + (size_t)tid * 12;
    float4 d[12];
#pragma unroll
    for (int i = 0; i < 12; i++) d[i] = ip[i];

    // ---------------- Phase 1: thread-local aggregate over 8 steps ----------------
    Carry C;
    set_identity(C);
#pragma unroll
    for (int g = 0; g < 4; g++) {
        float4 a0 = d[3*g], a1 = d[3*g+1], a2 = d[3*g+2];
        step_update(C, a0.x, a0.y, a0.z, a0.w, a1.x, a1.y);
        step_update(C, a1.z, a1.w, a2.x, a2.y, a2.z, a2.w);
    }

    // ---------------- Block-level inclusive scan (Hillis-Steele, 9 rounds) ----------------
    store_elem(s_buf + tid * 17, C);
    __syncthreads();

    for (int dd = 1; dd < NTH; dd <<= 1) {
        float L[15];
        const bool act = (tid >= dd);
        if (act) {
            const float* l = s_buf + (tid - dd) * 17;
#pragma unroll
            for (int i = 0; i < 15; i++) L[i] = l[i];
        }
        __syncthreads();
        if (act) {
            int cnt = dd < (tid + 1) ? dd : (tid + 1);   // span of C entering this round
            compose_left(C, L, (float)cnt * STEPDT);
            store_elem(s_buf + tid * 17, C);
        }
        __syncthreads();
    }

    // exclusive prefix = inclusive of tid-1
    if (tid == 0) set_identity(C);
    else {
        const float* l = s_buf + (tid - 1) * 17;
        C.R0=l[0]; C.R1=l[1]; C.R2=l[2]; C.R3=l[3]; C.R4=l[4]; C.R5=l[5];
        C.R6=l[6]; C.R7=l[7]; C.R8=l[8];
        C.vx=l[9]; C.vy=l[10]; C.vz=l[11];
        C.px=l[12]; C.py=l[13]; C.pz=l[14];
    }
    __syncthreads();   // scan buffer reads done before reuse as output staging

    // ---------------- Phase 2: replay from registers, staged + coalesced output ------------
    float4* out4 = (float4*)out + (size_t)b * (T_LEN * 4);

#pragma unroll
    for (int g = 0; g < 4; g++) {
        float4 a0 = d[3*g], a1 = d[3*g+1], a2 = d[3*g+2];
        float wxs[2] = {a0.x, a1.z};
        float wys[2] = {a0.y, a1.w};
        float wzs[2] = {a0.z, a2.x};
        float axs[2] = {a0.w, a2.y};
        float ays[2] = {a1.x, a2.z};
        float azs[2] = {a1.y, a2.w};

#pragma unroll
        for (int k = 0; k < 2; k++) {
            step_update(C, wxs[k], wys[k], wzs[k], axs[k], ays[k], azs[k]);

            // quaternion from R (half-angle identities; matches reference clip+EPS path)
            float tr = C.R0 + C.R4 + C.R8;
            float cc = 0.5f * (tr - 1.0f);
            cc = fminf(fmaxf(cc, -1.0f + 1e-7f), 1.0f - 1e-7f);
            float t   = 0.5f * (1.0f + cc);
            float rin = rsqrtf(t);
            float qw  = t * rin;
            float fq  = 0.25f * rin;
            float qx  = (C.R7 - C.R5) * fq;
            float qy  = (C.R2 - C.R6) * fq;
            float qz  = (C.R3 - C.R1) * fq;

            float* dst = s_buf + (k * 16) * PITCH + tid;
            dst[0*PITCH]  = wxs[k]; dst[1*PITCH]  = wys[k]; dst[2*PITCH]  = wzs[k];
            dst[3*PITCH]  = axs[k]; dst[4*PITCH]  = ays[k]; dst[5*PITCH]  = azs[k];
            dst[6*PITCH]  = C.px;   dst[7*PITCH]  = C.py;   dst[8*PITCH]  = C.pz;
            dst[9*PITCH]  = qw;     dst[10*PITCH] = qx;     dst[11*PITCH] = qy;
            dst[12*PITCH] = qz;
            dst[13*PITCH] = C.vx;   dst[14*PITCH] = C.vy;   dst[15*PITCH] = C.vz;
        }
        __syncthreads();

        // coalesced flush: 2 steps x 512 owners = 4096 float4, 8 per thread.
        // lane group covers full 128B lines -> 4 wavefronts per STG.128
#pragma unroll
        for (int r = 0; r < 8; r++) {
            int f  = tid + NTH * r;
            int o  = f >> 3;          // owner
            int mq = f & 7;           // float4 index within owner's 2-step chunk
            const float* s = s_buf + (mq * 4) * PITCH + o;
            float4 v = make_float4(s[0*PITCH], s[1*PITCH], s[2*PITCH], s[3*PITCH]);
            out4[(size_t)o * (PER * 4) + g * 8 + mq] = v;
        }
        __syncthreads();
    }
}

extern "C" void kernel_launch(void* const* d_in, const int* in_sizes, int n_in,
                              void* d_out, int out_size) {
    const float* in = (const float*)d_in[0];
    float* out = (float*)d_out;
    int Bn = in_sizes[0] / (T_LEN * 6);   // 512 for the reference shapes
    preint_kernel<<<Bn, NTH>>>(in, out);
}

// round 8
// speedup vs baseline: 1.4396x; 1.1103x over previous
#include <cuda_runtime.h>
#include <cstdint>

#define T_LEN  4096
#define NTH    512
#define PER    8                  // steps per thread; input held in registers
#define PITCH  513                // smem row pitch for output staging (513 % 32 == 1)

#define DTF    (1.0f / 200.0f)
#define DT2H   (DTF * DTF * 0.5f)
#define STEPDT ((float)PER * DTF)

// scan element: unit quaternion q (rotation), v, p.  Action on carry:
//   q' = q0 (x) q ; v' = v0 + rot(q0, v) ; p' = p0 + v0*span + rot(q0, p)
struct QC { float qw,qx,qy,qz, vx,vy,vz, px,py,pz; };

__device__ __forceinline__ void set_identity(QC& C) {
    C.qw=1.f; C.qx=0.f; C.qy=0.f; C.qz=0.f;
    C.vx=C.vy=C.vz=0.f; C.px=C.py=C.pz=0.f;
}

__device__ __forceinline__ void rot_q(float qw,float qx,float qy,float qz,
                                      float x,float y,float z,
                                      float& rx,float& ry,float& rz) {
    // rot(q, a) = a + qw*t + qv x t,  t = 2 qv x a   (unit q)
    float tx = 2.0f*(qy*z - qz*y);
    float ty = 2.0f*(qz*x - qx*z);
    float tz = 2.0f*(qx*y - qy*x);
    rx = x + qw*tx + (qy*tz - qz*ty);
    ry = y + qw*ty + (qz*tx - qx*tz);
    rz = z + qw*tz + (qx*ty - qy*tx);
}

// C = L compose C  (L earlier in time); span_r = time span covered by C
__device__ __forceinline__ void compose_left(QC& C, const QC& L, float span_r) {
    float qw = L.qw*C.qw - L.qx*C.qx - L.qy*C.qy - L.qz*C.qz;
    float qx = L.qw*C.qx + L.qx*C.qw + L.qy*C.qz - L.qz*C.qy;
    float qy = L.qw*C.qy - L.qx*C.qz + L.qy*C.qw + L.qz*C.qx;
    float qz = L.qw*C.qz + L.qx*C.qy - L.qy*C.qx + L.qz*C.qw;
    float rvx,rvy,rvz; rot_q(L.qw,L.qx,L.qy,L.qz, C.vx,C.vy,C.vz, rvx,rvy,rvz);
    float rpx,rpy,rpz; rot_q(L.qw,L.qx,L.qy,L.qz, C.px,C.py,C.pz, rpx,rpy,rpz);
    C.qw=qw; C.qx=qx; C.qy=qy; C.qz=qz;
    C.vx = L.vx + rvx;  C.vy = L.vy + rvy;  C.vz = L.vz + rvz;
    C.px = L.px + L.vx*span_r + rpx;
    C.py = L.py + L.vy*span_r + rpy;
    C.pz = L.pz + L.vz*span_r + rpz;
}

// one recurrence step in quaternion form
__device__ __forceinline__ void step_q(QC& C, float wx,float wy,float wz,
                                       float ax,float ay,float az) {
    // dq from axis-angle, Taylor (h = |w| dt / 2 <= ~0.02):
    float n2 = fmaf(wx,wx, fmaf(wy,wy, wz*wz));
    float h2 = n2 * (0.25f * DTF * DTF);
    float dqw = 1.0f - h2*(0.5f - h2*(1.0f/24.0f));
    float s   = (0.5f*DTF) * (1.0f - h2*(1.0f/6.0f - h2*(1.0f/120.0f)));
    float dqx = wx*s, dqy = wy*s, dqz = wz*s;

    float qw = C.qw*dqw - C.qx*dqx - C.qy*dqy - C.qz*dqz;
    float qx = C.qw*dqx + C.qx*dqw + C.qy*dqz - C.qz*dqy;
    float qy = C.qw*dqy - C.qx*dqz + C.qy*dqw + C.qz*dqx;
    float qz = C.qw*dqz + C.qx*dqy - C.qy*dqx + C.qz*dqw;
    C.qw=qw; C.qx=qx; C.qy=qy; C.qz=qz;

    float Rax,Ray,Raz; rot_q(qw,qx,qy,qz, ax,ay,az, Rax,Ray,Raz);

    C.vx += Rax*DTF; C.vy += Ray*DTF; C.vz += Raz*DTF;
    C.px += C.vx*DTF + Rax*DT2H;
    C.py += C.vy*DTF + Ray*DT2H;
    C.pz += C.vz*DTF + Raz*DT2H;
}

__device__ __forceinline__ QC shup(const QC& c, int d) {
    QC r;
    r.qw=__shfl_up_sync(0xffffffffu,c.qw,d);
    r.qx=__shfl_up_sync(0xffffffffu,c.qx,d);
    r.qy=__shfl_up_sync(0xffffffffu,c.qy,d);
    r.qz=__shfl_up_sync(0xffffffffu,c.qz,d);
    r.vx=__shfl_up_sync(0xffffffffu,c.vx,d);
    r.vy=__shfl_up_sync(0xffffffffu,c.vy,d);
    r.vz=__shfl_up_sync(0xffffffffu,c.vz,d);
    r.px=__shfl_up_sync(0xffffffffu,c.px,d);
    r.py=__shfl_up_sync(0xffffffffu,c.py,d);
    r.pz=__shfl_up_sync(0xffffffffu,c.pz,d);
    return r;
}

__device__ __forceinline__ void store_qc(float* m, const QC& C) {
    m[0]=C.qw; m[1]=C.qx; m[2]=C.qy; m[3]=C.qz;
    m[4]=C.vx; m[5]=C.vy; m[6]=C.vz;
    m[7]=C.px; m[8]=C.py; m[9]=C.pz;
}
__device__ __forceinline__ void load_qc(const float* m, QC& C) {
    C.qw=m[0]; C.qx=m[1]; C.qy=m[2]; C.qz=m[3];
    C.vx=m[4]; C.vy=m[5]; C.vz=m[6];
    C.px=m[7]; C.py=m[8]; C.pz=m[9];
}

__global__ void __launch_bounds__(NTH, 1)
preint_kernel(const float* __restrict__ in, float* __restrict__ out) {
    __shared__ float s_buf[32 * PITCH];   // output staging (phase 2 only)
    __shared__ float s_w[16 * 11];        // warp aggregates / prefixes

    const int b    = blockIdx.x;
    const int tid  = threadIdx.x;
    const int lane = tid & 31;
    const int wid  = tid >> 5;

    // ---------------- Load input ONCE into registers (12 float4 per thread) ----------------
    const float4* ip = (const float4*)in + (size_t)b * (T_LEN * 6 / 4) + (size_t)tid * 12;
    float4 d[12];
#pragma unroll
    for (int i = 0; i < 12; i++) d[i] = ip[i];

    // ---------------- Phase 1: thread-local aggregate over 8 steps ----------------
    QC C;
    set_identity(C);
#pragma unroll
    for (int g = 0; g < 4; g++) {
        float4 a0 = d[3*g], a1 = d[3*g+1], a2 = d[3*g+2];
        step_q(C, a0.x, a0.y, a0.z, a0.w, a1.x, a1.y);
        step_q(C, a1.z, a1.w, a2.x, a2.y, a2.z, a2.w);
    }

    // ---------------- Intra-warp inclusive scan (shuffles, no barriers) ----------------
#pragma unroll
    for (int dd = 1; dd < 32; dd <<= 1) {
        QC L = shup(C, dd);
        if (lane >= dd) compose_left(C, L, (float)dd * STEPDT);
    }

    // warp aggregate -> smem
    if (lane == 31) store_qc(s_w + wid * 11, C);
    __syncthreads();

    // ---------------- Inter-warp scan of 16 aggregates (warp 0) ----------------
    if (wid == 0) {
        QC A;
        if (lane < 16) load_qc(s_w + lane * 11, A);
        else           set_identity(A);
#pragma unroll
        for (int dd = 1; dd < 16; dd <<= 1) {
            QC L = shup(A, dd);
            if (lane >= dd && lane < 16) compose_left(A, L, (float)(dd * 32) * STEPDT);
        }
        if (lane < 16) store_qc(s_w + lane * 11, A);
    }
    __syncthreads();

    // ---------------- Per-thread exclusive prefix ----------------
    {
        QC E = shup(C, 1);
        if (lane == 0) set_identity(E);
        QC W;
        if (wid == 0) set_identity(W);
        else          load_qc(s_w + (wid - 1) * 11, W);
        compose_left(E, W, (float)(lane * PER) * DTF);
        C = E;
    }

    // ---------------- Phase 2: replay from registers, staged + coalesced output ------------
    float4* out4 = (float4*)out + (size_t)b * (T_LEN * 4);

#pragma unroll
    for (int g = 0; g < 4; g++) {
        float4 a0 = d[3*g], a1 = d[3*g+1], a2 = d[3*g+2];
        float wxs[2] = {a0.x, a1.z};
        float wys[2] = {a0.y, a1.w};
        float wzs[2] = {a0.z, a2.x};
        float axs[2] = {a0.w, a2.y};
        float ays[2] = {a1.x, a2.z};
        float azs[2] = {a1.y, a2.w};

#pragma unroll
        for (int k = 0; k < 2; k++) {
            step_q(C, wxs[k], wys[k], wzs[k], axs[k], ays[k], azs[k]);

            // output quaternion = carry, renormalized, sign-fixed (qw >= 0 like reference)
            float n  = fmaf(C.qw,C.qw, fmaf(C.qx,C.qx, fmaf(C.qy,C.qy, C.qz*C.qz)));
            float rn = rsqrtf(n);
            rn = (C.qw < 0.0f) ? -rn : rn;
            float qw = C.qw*rn, qx = C.qx*rn, qy = C.qy*rn, qz = C.qz*rn;

            float* dst = s_buf + (k * 16) * PITCH + tid;
            dst[0*PITCH]  = wxs[k]; dst[1*PITCH]  = wys[k]; dst[2*PITCH]  = wzs[k];
            dst[3*PITCH]  = axs[k]; dst[4*PITCH]  = ays[k]; dst[5*PITCH]  = azs[k];
            dst[6*PITCH]  = C.px;   dst[7*PITCH]  = C.py;   dst[8*PITCH]  = C.pz;
            dst[9*PITCH]  = qw;     dst[10*PITCH] = qx;     dst[11*PITCH] = qy;
            dst[12*PITCH] = qz;
            dst[13*PITCH] = C.vx;   dst[14*PITCH] = C.vy;   dst[15*PITCH] = C.vz;
        }
        __syncthreads();

        // coalesced flush: 2 steps x 512 owners = 4096 float4, 8 per thread
#pragma unroll
        for (int r = 0; r < 8; r++) {
            int f  = tid + NTH * r;
            int o  = f >> 3;
            int mq = f & 7;
            const float* s = s_buf + (mq * 4) * PITCH + o;
            float4 v = make_float4(s[0*PITCH], s[1*PITCH], s[2*PITCH], s[3*PITCH]);
            out4[(size_t)o * (PER * 4) + g * 8 + mq] = v;
        }
        __syncthreads();
    }
}

extern "C" void kernel_launch(void* const* d_in, const int* in_sizes, int n_in,
                              void* d_out, int out_size) {
    const float* in = (const float*)d_in[0];
    float* out = (float*)d_out;
    int Bn = in_sizes[0] / (T_LEN * 6);   // 512 for the reference shapes
    preint_kernel<<<Bn, NTH>>>(in, out);
}